// round 15
// baseline (speedup 1.0000x reference)
#include <cuda_runtime.h>
#include <cuda_fp16.h>
#include <stdint.h>

#define IN_SIZE  4096
#define OUT_SIZE 4096
#define BATCH    256

#define BK      64                 // k-elements per stage (fp16: 128B rows)
#define NSTAGE  (IN_SIZE / BK)     // 64
#define STAGES  4
#define A_BYTES 8192               // 64 rows x 128B
#define B_BYTES 16384              // 128 rows x 128B
#define STAGE_BYTES (A_BYTES + B_BYTES)
#define SMEM_BYTES (STAGES * STAGE_BYTES)

#define ZERO_BLOCKS 1024           // 32 MB: 1024 blk x 256 thr x 8 float4
#define CVTX_BLOCKS 1024           // 4 MB fp32 in / (256 thr * 16 B out)

// fp16 transposed weight g_Wh[out][in] — scattered into directly via f16x2 red.
__device__ __half g_Wh[(size_t)IN_SIZE * OUT_SIZE];
__device__ __half g_Xh[(size_t)BATCH * IN_SIZE];
__device__ int    g_idx_is64;

// ---------------------------------------------------------------------------
// helpers
// ---------------------------------------------------------------------------
__device__ __forceinline__ uint32_t smem_u32(const void* p) {
    uint32_t a;
    asm("{ .reg .u64 t; cvta.to.shared.u64 t, %1; cvt.u32.u64 %0, t; }"
        : "=r"(a) : "l"(p));
    return a;
}
__device__ __forceinline__ void cpa16(uint32_t s, const void* g) {
    asm volatile("cp.async.cg.shared.global [%0], [%1], 16;" :: "r"(s), "l"(g));
}
__device__ __forceinline__ void cpa_commit() {
    asm volatile("cp.async.commit_group;" ::: "memory");
}
template <int N>
__device__ __forceinline__ void cpa_wait() {
    asm volatile("cp.async.wait_group %0;" :: "n"(N) : "memory");
}
__device__ __forceinline__ void ldsm_x4(uint32_t& r0, uint32_t& r1,
                                        uint32_t& r2, uint32_t& r3, uint32_t a) {
    asm volatile("ldmatrix.sync.aligned.m8n8.x4.shared.b16 {%0,%1,%2,%3}, [%4];"
                 : "=r"(r0), "=r"(r1), "=r"(r2), "=r"(r3) : "r"(a));
}
__device__ __forceinline__ void mma_f16(float& d0, float& d1, float& d2, float& d3,
                                        uint32_t a0, uint32_t a1, uint32_t a2, uint32_t a3,
                                        uint32_t b0, uint32_t b1) {
    asm volatile(
        "mma.sync.aligned.m16n8k16.row.col.f32.f16.f16.f32 "
        "{%0,%1,%2,%3}, {%4,%5,%6,%7}, {%8,%9}, {%0,%1,%2,%3};"
        : "+f"(d0), "+f"(d1), "+f"(d2), "+f"(d3)
        : "r"(a0), "r"(a1), "r"(a2), "r"(a3), "r"(b0), "r"(b1));
}

// ---------------------------------------------------------------------------
// Prep: zero fp16 Wh (32 MB, 8 x float4 = 128 contiguous bytes per thread,
// one wave on chip) + idx dtype detection (block 0).
// ---------------------------------------------------------------------------
__global__ void prep_kernel(const uint32_t* __restrict__ idx_words) {
    float4* p = reinterpret_cast<float4*>(g_Wh) +
                ((size_t)blockIdx.x * blockDim.x + threadIdx.x) * 8;
    const float4 z = make_float4(0.f, 0.f, 0.f, 0.f);
#pragma unroll
    for (int j = 0; j < 8; ++j) p[j] = z;
    if (blockIdx.x == 0 && threadIdx.x == 0) {
        uint32_t acc = 0;
#pragma unroll
        for (int j = 0; j < 64; ++j) acc |= idx_words[2 * j + 1];
        g_idx_is64 = (acc == 0u) ? 1 : 0;
    }
}

// ---------------------------------------------------------------------------
// Scatter: g_Wh[col][row] += fp16(val) via explicit no-return red
// (red.global.add.noftz.f16x2 on the aligned 32-bit word; neighbor lane +0.0).
// Blocks [0, CVTX_BLOCKS) convert X -> fp16 instead (independent of W).
// ---------------------------------------------------------------------------
__device__ __forceinline__ void scat1(uint32_t row, uint32_t col, float v) {
    const uint32_t cell = col * (uint32_t)IN_SIZE + row;
    uint32_t hv = (uint32_t)__half_as_ushort(__float2half_rn(v));
    hv <<= (cell & 1u) << 4;
    asm volatile("red.global.add.noftz.f16x2 [%0], %1;"
                 :: "l"(reinterpret_cast<__half2*>(g_Wh) + (cell >> 1)), "r"(hv)
                 : "memory");
}

__global__ void scatter_cvtx_kernel(const void* __restrict__ idx,
                                    const float* __restrict__ val,
                                    const float* __restrict__ X,
                                    int nnz) {
    const int b = blockIdx.x;
    if (b < CVTX_BLOCKS) {
        size_t i = (size_t)b * blockDim.x + threadIdx.x;
        float4 v = reinterpret_cast<const float4*>(X)[i];
        __half2 h0 = __floats2half2_rn(v.x, v.y);
        __half2 h1 = __floats2half2_rn(v.z, v.w);
        reinterpret_cast<__half2*>(g_Xh)[2 * i + 0] = h0;
        reinterpret_cast<__half2*>(g_Xh)[2 * i + 1] = h1;
        return;
    }

    const int base = ((b - CVTX_BLOCKS) * blockDim.x + threadIdx.x) * 8;
    if (base >= nnz) return;
    const int is64 = g_idx_is64;

    if (base + 8 <= nnz) {
        float4 va = *reinterpret_cast<const float4*>(val + base);
        float4 vb = *reinterpret_cast<const float4*>(val + base + 4);
        float v[8] = {va.x, va.y, va.z, va.w, vb.x, vb.y, vb.z, vb.w};
        uint32_t row[8], col[8];
        if (is64) {
            const longlong2* p = reinterpret_cast<const longlong2*>(idx) + base;
#pragma unroll
            for (int j = 0; j < 8; ++j) {
                longlong2 e = p[j];
                row[j] = (uint32_t)e.x;
                col[j] = (uint32_t)e.y;
            }
        } else {
            const int4* p = reinterpret_cast<const int4*>(idx) + base / 2;
#pragma unroll
            for (int j = 0; j < 4; ++j) {
                int4 e = p[j];
                row[2 * j]     = (uint32_t)e.x; col[2 * j]     = (uint32_t)e.y;
                row[2 * j + 1] = (uint32_t)e.z; col[2 * j + 1] = (uint32_t)e.w;
            }
        }
#pragma unroll
        for (int j = 0; j < 8; ++j) scat1(row[j], col[j], v[j]);
    } else {
        for (int i = base; i < nnz; ++i) {
            uint32_t row, col;
            if (is64) {
                longlong2 p = reinterpret_cast<const longlong2*>(idx)[i];
                row = (uint32_t)p.x; col = (uint32_t)p.y;
            } else {
                int2 p = reinterpret_cast<const int2*>(idx)[i];
                row = (uint32_t)p.x; col = (uint32_t)p.y;
            }
            scat1(row, col, val[i]);
        }
    }
}

// ---------------------------------------------------------------------------
// fp16 mma.sync GEMM (validated): out = relu(X @ Wh^T + bias)
// CTA 64x128, 128 threads = 4 warps (2m x 2n), warp tile 32x64.
// m16n8k16, K staged 64/iter, 64 stages, 4-stage cp.async pipeline.
// ---------------------------------------------------------------------------
__global__ __launch_bounds__(128, 1)
void gemm_f16_mma(const float* __restrict__ bias, float* __restrict__ out) {
    extern __shared__ uint32_t smu[];
    const uint32_t sbase0 = smem_u32(smu);

    const int tid   = threadIdx.x;
    const int lane  = tid & 31;
    const int wid   = tid >> 5;
    const int warpm = wid & 1;
    const int warpn = wid >> 1;
    const int m0 = blockIdx.y * 64;
    const int n0 = blockIdx.x * 128;

    const int srow = tid >> 3;
    const int sj   = tid & 7;

    const __half* Ag = g_Xh + (size_t)(m0 + srow) * IN_SIZE + sj * 8;
    const __half* Bg = g_Wh + (size_t)(n0 + srow) * IN_SIZE + sj * 8;

    const uint32_t swz = (uint32_t)((sj ^ (srow & 7)) << 4);
    uint32_t offA[4], offB[8];
#pragma unroll
    for (int i = 0; i < 4; ++i)
        offA[i] = (uint32_t)((srow + 16 * i) * 128) + swz;
#pragma unroll
    for (int i = 0; i < 8; ++i)
        offB[i] = A_BYTES + (uint32_t)((srow + 16 * i) * 128) + swz;

    const int l7 = lane & 7;
    const int qa = lane >> 4;
    const int qb = (lane >> 3) & 1;
    uint32_t rAbase[2];
#pragma unroll
    for (int msub = 0; msub < 2; ++msub)
        rAbase[msub] = (uint32_t)((warpm * 32 + msub * 16 +
                                   ((lane >> 3) & 1) * 8 + l7) * 128);
    uint32_t rBbase[4];
#pragma unroll
    for (int p = 0; p < 4; ++p)
        rBbase[p] = (uint32_t)((warpn * 64 + p * 16 + ((lane >> 4) << 3) + l7) * 128);

    float acc[2][8][4];
#pragma unroll
    for (int a = 0; a < 2; ++a)
#pragma unroll
        for (int b = 0; b < 8; ++b)
#pragma unroll
            for (int d = 0; d < 4; ++d) acc[a][b][d] = 0.f;

#pragma unroll
    for (int ps = 0; ps < 3; ++ps) {
        const uint32_t sb = sbase0 + (uint32_t)ps * STAGE_BYTES;
#pragma unroll
        for (int i = 0; i < 4; ++i)
            cpa16(sb + offA[i], Ag + (size_t)(16 * i) * IN_SIZE + ps * BK);
#pragma unroll
        for (int i = 0; i < 8; ++i)
            cpa16(sb + offB[i], Bg + (size_t)(16 * i) * IN_SIZE + ps * BK);
        cpa_commit();
    }

    for (int s = 0; s < NSTAGE; ++s) {
        cpa_wait<2>();
        __syncthreads();

        if (s + 3 < NSTAGE) {
            const uint32_t nb = sbase0 + (uint32_t)((s + 3) & 3) * STAGE_BYTES;
            const int ko = (s + 3) * BK;
#pragma unroll
            for (int i = 0; i < 4; ++i)
                cpa16(nb + offA[i], Ag + (size_t)(16 * i) * IN_SIZE + ko);
#pragma unroll
            for (int i = 0; i < 8; ++i)
                cpa16(nb + offB[i], Bg + (size_t)(16 * i) * IN_SIZE + ko);
        }
        cpa_commit();

        const uint32_t sb = sbase0 + (uint32_t)(s & 3) * STAGE_BYTES;
#pragma unroll
        for (int ks = 0; ks < 4; ++ks) {
            const uint32_t aswz = (uint32_t)(((ks * 2 + qa) ^ l7) << 4);
            const uint32_t bswz = (uint32_t)(((ks * 2 + qb) ^ l7) << 4);
            uint32_t af[2][4];
#pragma unroll
            for (int msub = 0; msub < 2; ++msub)
                ldsm_x4(af[msub][0], af[msub][1], af[msub][2], af[msub][3],
                        sb + rAbase[msub] + aswz);
            uint32_t bf[8][2];
#pragma unroll
            for (int p = 0; p < 4; ++p)
                ldsm_x4(bf[2 * p][0], bf[2 * p][1], bf[2 * p + 1][0], bf[2 * p + 1][1],
                        sb + A_BYTES + rBbase[p] + bswz);
#pragma unroll
            for (int msub = 0; msub < 2; ++msub)
#pragma unroll
                for (int nsub = 0; nsub < 8; ++nsub)
                    mma_f16(acc[msub][nsub][0], acc[msub][nsub][1],
                            acc[msub][nsub][2], acc[msub][nsub][3],
                            af[msub][0], af[msub][1], af[msub][2], af[msub][3],
                            bf[nsub][0], bf[nsub][1]);
        }
    }

#pragma unroll
    for (int msub = 0; msub < 2; ++msub) {
        const int m = m0 + warpm * 32 + msub * 16 + (lane >> 2);
#pragma unroll
        for (int nsub = 0; nsub < 8; ++nsub) {
            const int n = n0 + warpn * 64 + nsub * 8 + (lane & 3) * 2;
            float2 bv = *reinterpret_cast<const float2*>(bias + n);
            float2 o0, o1;
            o0.x = fmaxf(acc[msub][nsub][0] + bv.x, 0.f);
            o0.y = fmaxf(acc[msub][nsub][1] + bv.y, 0.f);
            o1.x = fmaxf(acc[msub][nsub][2] + bv.x, 0.f);
            o1.y = fmaxf(acc[msub][nsub][3] + bv.y, 0.f);
            *reinterpret_cast<float2*>(out + (size_t)m * OUT_SIZE + n)       = o0;
            *reinterpret_cast<float2*>(out + (size_t)(m + 8) * OUT_SIZE + n) = o1;
        }
    }
}

// ---------------------------------------------------------------------------
// kernel_launch
// ---------------------------------------------------------------------------
extern "C" void kernel_launch(void* const* d_in, const int* in_sizes, int n_in,
                              void* d_out, int out_size) {
    const float* X    = (const float*)d_in[0];
    const void*  idx  = d_in[1];
    const float* val  = (const float*)d_in[2];
    const float* bias = (const float*)d_in[3];
    float*       out  = (float*)d_out;

    const int nnz = in_sizes[2];

    prep_kernel<<<ZERO_BLOCKS, 256>>>((const uint32_t*)idx);
    const int scat_blocks = (nnz / 8 + 255) / 256;
    scatter_cvtx_kernel<<<CVTX_BLOCKS + scat_blocks, 256>>>(idx, val, X, nnz);

    cudaFuncSetAttribute(gemm_f16_mma,
                         cudaFuncAttributeMaxDynamicSharedMemorySize, SMEM_BYTES);
    dim3 grid(OUT_SIZE / 128, BATCH / 64);   // (32, 4) = 128 CTAs
    gemm_f16_mma<<<grid, 128, SMEM_BYTES>>>(bias, out);
}

// round 16
// speedup vs baseline: 1.0524x; 1.0524x over previous
#include <cuda_runtime.h>
#include <cuda_fp16.h>
#include <stdint.h>

#define IN_SIZE  4096
#define OUT_SIZE 4096
#define BATCH    256

#define BK      64                 // k-elements per stage (fp16: 128B rows)
#define NSTAGE  (IN_SIZE / BK)     // 64
#define STAGES  4
#define A_BYTES 8192               // 64 rows x 128B
#define B_BYTES 16384              // 128 rows x 128B
#define STAGE_BYTES (A_BYTES + B_BYTES)
#define SMEM_BYTES (STAGES * STAGE_BYTES)

#define ZERO_BLOCKS 1024           // 32 MB: 1024 blk x 32KB slab (coalesced)
#define CVTX_BLOCKS 1024           // 4 MB fp32 in / (256 thr * 16 B out)

// fp16 transposed weight g_Wh[out][in] — scattered into directly via f16x2 red.
__device__ __half g_Wh[(size_t)IN_SIZE * OUT_SIZE];
__device__ __half g_Xh[(size_t)BATCH * IN_SIZE];
__device__ int    g_idx_is64;

// ---------------------------------------------------------------------------
// helpers
// ---------------------------------------------------------------------------
__device__ __forceinline__ uint32_t smem_u32(const void* p) {
    uint32_t a;
    asm("{ .reg .u64 t; cvta.to.shared.u64 t, %1; cvt.u32.u64 %0, t; }"
        : "=r"(a) : "l"(p));
    return a;
}
__device__ __forceinline__ void cpa16(uint32_t s, const void* g) {
    asm volatile("cp.async.cg.shared.global [%0], [%1], 16;" :: "r"(s), "l"(g));
}
__device__ __forceinline__ void cpa_commit() {
    asm volatile("cp.async.commit_group;" ::: "memory");
}
template <int N>
__device__ __forceinline__ void cpa_wait() {
    asm volatile("cp.async.wait_group %0;" :: "n"(N) : "memory");
}
__device__ __forceinline__ void ldsm_x4(uint32_t& r0, uint32_t& r1,
                                        uint32_t& r2, uint32_t& r3, uint32_t a) {
    asm volatile("ldmatrix.sync.aligned.m8n8.x4.shared.b16 {%0,%1,%2,%3}, [%4];"
                 : "=r"(r0), "=r"(r1), "=r"(r2), "=r"(r3) : "r"(a));
}
__device__ __forceinline__ void mma_f16(float& d0, float& d1, float& d2, float& d3,
                                        uint32_t a0, uint32_t a1, uint32_t a2, uint32_t a3,
                                        uint32_t b0, uint32_t b1) {
    asm volatile(
        "mma.sync.aligned.m16n8k16.row.col.f32.f16.f16.f32 "
        "{%0,%1,%2,%3}, {%4,%5,%6,%7}, {%8,%9}, {%0,%1,%2,%3};"
        : "+f"(d0), "+f"(d1), "+f"(d2), "+f"(d3)
        : "r"(a0), "r"(a1), "r"(a2), "r"(a3), "r"(b0), "r"(b1));
}

// ---------------------------------------------------------------------------
// Prep: zero fp16 Wh (32 MB). Block b owns a contiguous 32 KB slab; thread
// writes slab[j*256 + tid] (each STG.128 warp-coalesced over 4 KB).
// One wave on chip, 8 independent stores per thread. + idx dtype detection.
// ---------------------------------------------------------------------------
__global__ void prep_kernel(const uint32_t* __restrict__ idx_words) {
    float4* slab = reinterpret_cast<float4*>(g_Wh) + (size_t)blockIdx.x * 2048;
    const float4 z = make_float4(0.f, 0.f, 0.f, 0.f);
#pragma unroll
    for (int j = 0; j < 8; ++j)
        slab[j * 256 + threadIdx.x] = z;
    if (blockIdx.x == 0 && threadIdx.x == 0) {
        uint32_t acc = 0;
#pragma unroll
        for (int j = 0; j < 64; ++j) acc |= idx_words[2 * j + 1];
        g_idx_is64 = (acc == 0u) ? 1 : 0;
    }
}

// ---------------------------------------------------------------------------
// Scatter: g_Wh[col][row] += fp16(val) via explicit no-return red
// (red.global.add.noftz.f16x2 on the aligned 32-bit word; neighbor lane +0.0).
// Blocks [0, CVTX_BLOCKS) convert X -> fp16 instead (independent of W).
// ---------------------------------------------------------------------------
__device__ __forceinline__ void scat1(uint32_t row, uint32_t col, float v) {
    const uint32_t cell = col * (uint32_t)IN_SIZE + row;
    uint32_t hv = (uint32_t)__half_as_ushort(__float2half_rn(v));
    hv <<= (cell & 1u) << 4;
    asm volatile("red.global.add.noftz.f16x2 [%0], %1;"
                 :: "l"(reinterpret_cast<__half2*>(g_Wh) + (cell >> 1)), "r"(hv)
                 : "memory");
}

__global__ void scatter_cvtx_kernel(const void* __restrict__ idx,
                                    const float* __restrict__ val,
                                    const float* __restrict__ X,
                                    int nnz) {
    const int b = blockIdx.x;
    if (b < CVTX_BLOCKS) {
        size_t i = (size_t)b * blockDim.x + threadIdx.x;
        float4 v = reinterpret_cast<const float4*>(X)[i];
        __half2 h0 = __floats2half2_rn(v.x, v.y);
        __half2 h1 = __floats2half2_rn(v.z, v.w);
        reinterpret_cast<__half2*>(g_Xh)[2 * i + 0] = h0;
        reinterpret_cast<__half2*>(g_Xh)[2 * i + 1] = h1;
        return;
    }

    const int base = ((b - CVTX_BLOCKS) * blockDim.x + threadIdx.x) * 8;
    if (base >= nnz) return;
    const int is64 = g_idx_is64;

    if (base + 8 <= nnz) {
        float4 va = *reinterpret_cast<const float4*>(val + base);
        float4 vb = *reinterpret_cast<const float4*>(val + base + 4);
        float v[8] = {va.x, va.y, va.z, va.w, vb.x, vb.y, vb.z, vb.w};
        uint32_t row[8], col[8];
        if (is64) {
            const longlong2* p = reinterpret_cast<const longlong2*>(idx) + base;
#pragma unroll
            for (int j = 0; j < 8; ++j) {
                longlong2 e = p[j];
                row[j] = (uint32_t)e.x;
                col[j] = (uint32_t)e.y;
            }
        } else {
            const int4* p = reinterpret_cast<const int4*>(idx) + base / 2;
#pragma unroll
            for (int j = 0; j < 4; ++j) {
                int4 e = p[j];
                row[2 * j]     = (uint32_t)e.x; col[2 * j]     = (uint32_t)e.y;
                row[2 * j + 1] = (uint32_t)e.z; col[2 * j + 1] = (uint32_t)e.w;
            }
        }
#pragma unroll
        for (int j = 0; j < 8; ++j) scat1(row[j], col[j], v[j]);
    } else {
        for (int i = base; i < nnz; ++i) {
            uint32_t row, col;
            if (is64) {
                longlong2 p = reinterpret_cast<const longlong2*>(idx)[i];
                row = (uint32_t)p.x; col = (uint32_t)p.y;
            } else {
                int2 p = reinterpret_cast<const int2*>(idx)[i];
                row = (uint32_t)p.x; col = (uint32_t)p.y;
            }
            scat1(row, col, val[i]);
        }
    }
}

// ---------------------------------------------------------------------------
// fp16 mma.sync GEMM (validated): out = relu(X @ Wh^T + bias)
// CTA 64x128, 128 threads = 4 warps (2m x 2n), warp tile 32x64.
// m16n8k16, K staged 64/iter, 64 stages, 4-stage cp.async pipeline.
// ---------------------------------------------------------------------------
__global__ __launch_bounds__(128, 1)
void gemm_f16_mma(const float* __restrict__ bias, float* __restrict__ out) {
    extern __shared__ uint32_t smu[];
    const uint32_t sbase0 = smem_u32(smu);

    const int tid   = threadIdx.x;
    const int lane  = tid & 31;
    const int wid   = tid >> 5;
    const int warpm = wid & 1;
    const int warpn = wid >> 1;
    const int m0 = blockIdx.y * 64;
    const int n0 = blockIdx.x * 128;

    const int srow = tid >> 3;
    const int sj   = tid & 7;

    const __half* Ag = g_Xh + (size_t)(m0 + srow) * IN_SIZE + sj * 8;
    const __half* Bg = g_Wh + (size_t)(n0 + srow) * IN_SIZE + sj * 8;

    const uint32_t swz = (uint32_t)((sj ^ (srow & 7)) << 4);
    uint32_t offA[4], offB[8];
#pragma unroll
    for (int i = 0; i < 4; ++i)
        offA[i] = (uint32_t)((srow + 16 * i) * 128) + swz;
#pragma unroll
    for (int i = 0; i < 8; ++i)
        offB[i] = A_BYTES + (uint32_t)((srow + 16 * i) * 128) + swz;

    const int l7 = lane & 7;
    const int qa = lane >> 4;
    const int qb = (lane >> 3) & 1;
    uint32_t rAbase[2];
#pragma unroll
    for (int msub = 0; msub < 2; ++msub)
        rAbase[msub] = (uint32_t)((warpm * 32 + msub * 16 +
                                   ((lane >> 3) & 1) * 8 + l7) * 128);
    uint32_t rBbase[4];
#pragma unroll
    for (int p = 0; p < 4; ++p)
        rBbase[p] = (uint32_t)((warpn * 64 + p * 16 + ((lane >> 4) << 3) + l7) * 128);

    float acc[2][8][4];
#pragma unroll
    for (int a = 0; a < 2; ++a)
#pragma unroll
        for (int b = 0; b < 8; ++b)
#pragma unroll
            for (int d = 0; d < 4; ++d) acc[a][b][d] = 0.f;

#pragma unroll
    for (int ps = 0; ps < 3; ++ps) {
        const uint32_t sb = sbase0 + (uint32_t)ps * STAGE_BYTES;
#pragma unroll
        for (int i = 0; i < 4; ++i)
            cpa16(sb + offA[i], Ag + (size_t)(16 * i) * IN_SIZE + ps * BK);
#pragma unroll
        for (int i = 0; i < 8; ++i)
            cpa16(sb + offB[i], Bg + (size_t)(16 * i) * IN_SIZE + ps * BK);
        cpa_commit();
    }

    for (int s = 0; s < NSTAGE; ++s) {
        cpa_wait<2>();
        __syncthreads();

        if (s + 3 < NSTAGE) {
            const uint32_t nb = sbase0 + (uint32_t)((s + 3) & 3) * STAGE_BYTES;
            const int ko = (s + 3) * BK;
#pragma unroll
            for (int i = 0; i < 4; ++i)
                cpa16(nb + offA[i], Ag + (size_t)(16 * i) * IN_SIZE + ko);
#pragma unroll
            for (int i = 0; i < 8; ++i)
                cpa16(nb + offB[i], Bg + (size_t)(16 * i) * IN_SIZE + ko);
        }
        cpa_commit();

        const uint32_t sb = sbase0 + (uint32_t)(s & 3) * STAGE_BYTES;
#pragma unroll
        for (int ks = 0; ks < 4; ++ks) {
            const uint32_t aswz = (uint32_t)(((ks * 2 + qa) ^ l7) << 4);
            const uint32_t bswz = (uint32_t)(((ks * 2 + qb) ^ l7) << 4);
            uint32_t af[2][4];
#pragma unroll
            for (int msub = 0; msub < 2; ++msub)
                ldsm_x4(af[msub][0], af[msub][1], af[msub][2], af[msub][3],
                        sb + rAbase[msub] + aswz);
            uint32_t bf[8][2];
#pragma unroll
            for (int p = 0; p < 4; ++p)
                ldsm_x4(bf[2 * p][0], bf[2 * p][1], bf[2 * p + 1][0], bf[2 * p + 1][1],
                        sb + A_BYTES + rBbase[p] + bswz);
#pragma unroll
            for (int msub = 0; msub < 2; ++msub)
#pragma unroll
                for (int nsub = 0; nsub < 8; ++nsub)
                    mma_f16(acc[msub][nsub][0], acc[msub][nsub][1],
                            acc[msub][nsub][2], acc[msub][nsub][3],
                            af[msub][0], af[msub][1], af[msub][2], af[msub][3],
                            bf[nsub][0], bf[nsub][1]);
        }
    }

#pragma unroll
    for (int msub = 0; msub < 2; ++msub) {
        const int m = m0 + warpm * 32 + msub * 16 + (lane >> 2);
#pragma unroll
        for (int nsub = 0; nsub < 8; ++nsub) {
            const int n = n0 + warpn * 64 + nsub * 8 + (lane & 3) * 2;
            float2 bv = *reinterpret_cast<const float2*>(bias + n);
            float2 o0, o1;
            o0.x = fmaxf(acc[msub][nsub][0] + bv.x, 0.f);
            o0.y = fmaxf(acc[msub][nsub][1] + bv.y, 0.f);
            o1.x = fmaxf(acc[msub][nsub][2] + bv.x, 0.f);
            o1.y = fmaxf(acc[msub][nsub][3] + bv.y, 0.f);
            *reinterpret_cast<float2*>(out + (size_t)m * OUT_SIZE + n)       = o0;
            *reinterpret_cast<float2*>(out + (size_t)(m + 8) * OUT_SIZE + n) = o1;
        }
    }
}

// ---------------------------------------------------------------------------
// kernel_launch
// ---------------------------------------------------------------------------
extern "C" void kernel_launch(void* const* d_in, const int* in_sizes, int n_in,
                              void* d_out, int out_size) {
    const float* X    = (const float*)d_in[0];
    const void*  idx  = d_in[1];
    const float* val  = (const float*)d_in[2];
    const float* bias = (const float*)d_in[3];
    float*       out  = (float*)d_out;

    const int nnz = in_sizes[2];

    prep_kernel<<<ZERO_BLOCKS, 256>>>((const uint32_t*)idx);
    const int scat_blocks = (nnz / 8 + 255) / 256;
    scatter_cvtx_kernel<<<CVTX_BLOCKS + scat_blocks, 256>>>(idx, val, X, nnz);

    cudaFuncSetAttribute(gemm_f16_mma,
                         cudaFuncAttributeMaxDynamicSharedMemorySize, SMEM_BYTES);
    dim3 grid(OUT_SIZE / 128, BATCH / 64);   // (32, 4) = 128 CTAs
    gemm_f16_mma<<<grid, 128, SMEM_BYTES>>>(bias, out);
}